// round 5
// baseline (speedup 1.0000x reference)
#include <cuda_runtime.h>

#define N_PTS   800000
#define B_SEG   16
#define PTS     50000
#define C_IN    32
#define C_HID   16
#define EPS_BN  1e-5f
#define EPS_NRM 1e-12f

#define GRID1   592
#define CHUNK1  ((N_PTS + GRID1 - 1) / GRID1)   // 1352

#define BPS     37                               // blocks per segment, pass2
#define GRID2   (B_SEG * BPS)                    // 592 = 4 waves of 148
#define CHUNK2  ((PTS + BPS - 1) / BPS)          // 1352
#define TP      128                              // pass2 tile (points)

// ---------------- device scratch (allocation-free; zeroed every launch) ----
__device__ float g_sum_h [C_HID];
__device__ float g_sum_h2[C_HID];
__device__ float g_W1f   [C_HID * C_IN];
__device__ float g_b1f   [C_HID];
__device__ float g_sum_a;
__device__ float g_sum_a2;
__device__ float g_seg_xa[B_SEG][C_IN];
__device__ float g_seg_x [B_SEG][C_IN];
__device__ unsigned g_tick1, g_tick2;

// ---------------------------------------------------------------- zero ----
__global__ void zero_kernel() {
    int t = threadIdx.x;
    for (int i = t; i < C_HID; i += blockDim.x) { g_sum_h[i] = 0.f; g_sum_h2[i] = 0.f; }
    if (t == 0) { g_sum_a = 0.f; g_sum_a2 = 0.f; g_tick1 = 0u; g_tick2 = 0u; }
    for (int i = t; i < B_SEG * C_IN; i += blockDim.x) {
        ((float*)g_seg_xa)[i] = 0.f;
        ((float*)g_seg_x )[i] = 0.f;
    }
}

// -------------------- pass1: Sum h, Sum h^2, then fold BN1 (last block) ----
// thread = (point-lane pl = tid>>4, channel j = tid&15). W row in registers.
__global__ void __launch_bounds__(256, 3)
pass1_kernel(const float* __restrict__ x,
             const float* __restrict__ W1,
             const float* __restrict__ b1,
             const float* __restrict__ gamma1,
             const float* __restrict__ beta1) {
    __shared__ float red1[8 * C_HID];
    __shared__ float red2[8 * C_HID];
    __shared__ bool  sLast;
    int tid = threadIdx.x;
    int j   = tid & 15;
    int pl  = tid >> 4;

    // W1 row for this thread's channel j — registers, no smem in the loop
    const float4* wp = (const float4*)(W1 + j * C_IN);
    float4 w0 = wp[0], w1 = wp[1], w2 = wp[2], w3 = wp[3];
    float4 w4 = wp[4], w5 = wp[5], w6 = wp[6], w7 = wp[7];
    float  bj = b1[j];

    int start = blockIdx.x * CHUNK1;
    int end   = min(N_PTS, start + CHUNK1);

    float sh = 0.f, sh2 = 0.f;
    for (int i = start + pl; i < end; i += 16) {
        const float4* xv = (const float4*)(x + (size_t)i * C_IN);
        float s = bj;
        float4 v;
        v = xv[0]; s = fmaf(v.x,w0.x,s); s = fmaf(v.y,w0.y,s); s = fmaf(v.z,w0.z,s); s = fmaf(v.w,w0.w,s);
        v = xv[1]; s = fmaf(v.x,w1.x,s); s = fmaf(v.y,w1.y,s); s = fmaf(v.z,w1.z,s); s = fmaf(v.w,w1.w,s);
        v = xv[2]; s = fmaf(v.x,w2.x,s); s = fmaf(v.y,w2.y,s); s = fmaf(v.z,w2.z,s); s = fmaf(v.w,w2.w,s);
        v = xv[3]; s = fmaf(v.x,w3.x,s); s = fmaf(v.y,w3.y,s); s = fmaf(v.z,w3.z,s); s = fmaf(v.w,w3.w,s);
        v = xv[4]; s = fmaf(v.x,w4.x,s); s = fmaf(v.y,w4.y,s); s = fmaf(v.z,w4.z,s); s = fmaf(v.w,w4.w,s);
        v = xv[5]; s = fmaf(v.x,w5.x,s); s = fmaf(v.y,w5.y,s); s = fmaf(v.z,w5.z,s); s = fmaf(v.w,w5.w,s);
        v = xv[6]; s = fmaf(v.x,w6.x,s); s = fmaf(v.y,w6.y,s); s = fmaf(v.z,w6.z,s); s = fmaf(v.w,w6.w,s);
        v = xv[7]; s = fmaf(v.x,w7.x,s); s = fmaf(v.y,w7.y,s); s = fmaf(v.z,w7.z,s); s = fmaf(v.w,w7.w,s);
        sh  += s;
        sh2  = fmaf(s, s, sh2);
    }

    // combine the two point-lanes within each warp (lane ^ 16, same j)
    sh  += __shfl_xor_sync(0xffffffffu, sh,  16);
    sh2 += __shfl_xor_sync(0xffffffffu, sh2, 16);
    int lane = tid & 31, w = tid >> 5;
    if (lane < 16) { red1[w * 16 + lane] = sh; red2[w * 16 + lane] = sh2; }
    __syncthreads();
    if (tid < C_HID) {
        float a = 0.f, b = 0.f;
#pragma unroll
        for (int ww = 0; ww < 8; ww++) { a += red1[ww * 16 + tid]; b += red2[ww * 16 + tid]; }
        atomicAdd(&g_sum_h [tid], a);
        atomicAdd(&g_sum_h2[tid], b);
    }

    // ---- last block folds BN1 into W1', b1' ----
    __threadfence();
    __syncthreads();
    if (tid == 0) sLast = (atomicAdd(&g_tick1, 1u) == (unsigned)(gridDim.x - 1));
    __syncthreads();
    if (sLast) {
        __shared__ float sInv[C_HID];
        if (tid < C_HID) {
            float m   = g_sum_h [tid] * (1.f / N_PTS);
            float vv  = g_sum_h2[tid] * (1.f / N_PTS) - m * m;
            float inv = rsqrtf(vv + EPS_BN) * gamma1[tid];
            sInv[tid] = inv;
            g_b1f[tid] = (b1[tid] - m) * inv + beta1[tid];
        }
        __syncthreads();
        for (int idx = tid; idx < C_HID * C_IN; idx += 256)
            g_W1f[idx] = W1[idx] * sInv[idx >> 5];
    }
}

// ---- pass2: a_pre stats + per-segment sums, then finalize (last block) ----
__global__ void __launch_bounds__(256, 3)
pass2_kernel(const float* __restrict__ x,
             const float* __restrict__ W2,
             const float* __restrict__ b2,
             const float* __restrict__ gamma2,
             const float* __restrict__ beta2,
             const int*   __restrict__ length,
             float*       __restrict__ out) {
    __shared__ float as_[TP];
    __shared__ float r_axa[8 * C_IN];
    __shared__ float r_ax [8 * C_IN];
    __shared__ float r_sa [16];
    __shared__ float r_sa2[16];
    __shared__ bool  sLast;
    int tid = threadIdx.x;
    int j   = tid & 15;
    int pl  = tid >> 4;
    int c   = tid & 31;
    int pg  = tid >> 5;

    // folded W1' row for channel j — registers
    const float4* wp = (const float4*)(g_W1f + j * C_IN);
    float4 w0 = wp[0], w1 = wp[1], w2 = wp[2], w3 = wp[3];
    float4 w4 = wp[4], w5 = wp[5], w6 = wp[6], w7 = wp[7];
    float  bj  = g_b1f[j];
    float  w2j = W2[j];
    float  b20 = b2[0];

    int seg   = blockIdx.x / BPS;
    int blk   = blockIdx.x % BPS;
    int start = seg * PTS + blk * CHUNK2;
    int end   = min(seg * PTS + PTS, start + CHUNK2);

    float sa = 0.f, sa2 = 0.f, axa = 0.f, ax = 0.f;

    for (int ts = start; ts < end; ts += TP) {
        int tn = min(TP, end - ts);            // uniform across block

        // ---- Phase A: attention scalar per point (uniform trip count) ----
        int iters = (tn + 15) >> 4;
        for (int it = 0; it < iters; it++) {
            int p = pl + (it << 4);
            bool valid = p < tn;
            float r = 0.f;
            if (valid) {
                const float4* xv = (const float4*)(x + (size_t)(ts + p) * C_IN);
                float s = bj;
                float4 v;
                v = xv[0]; s = fmaf(v.x,w0.x,s); s = fmaf(v.y,w0.y,s); s = fmaf(v.z,w0.z,s); s = fmaf(v.w,w0.w,s);
                v = xv[1]; s = fmaf(v.x,w1.x,s); s = fmaf(v.y,w1.y,s); s = fmaf(v.z,w1.z,s); s = fmaf(v.w,w1.w,s);
                v = xv[2]; s = fmaf(v.x,w2.x,s); s = fmaf(v.y,w2.y,s); s = fmaf(v.z,w2.z,s); s = fmaf(v.w,w2.w,s);
                v = xv[3]; s = fmaf(v.x,w3.x,s); s = fmaf(v.y,w3.y,s); s = fmaf(v.z,w3.z,s); s = fmaf(v.w,w3.w,s);
                v = xv[4]; s = fmaf(v.x,w4.x,s); s = fmaf(v.y,w4.y,s); s = fmaf(v.z,w4.z,s); s = fmaf(v.w,w4.w,s);
                v = xv[5]; s = fmaf(v.x,w5.x,s); s = fmaf(v.y,w5.y,s); s = fmaf(v.z,w5.z,s); s = fmaf(v.w,w5.w,s);
                v = xv[6]; s = fmaf(v.x,w6.x,s); s = fmaf(v.y,w6.y,s); s = fmaf(v.z,w6.z,s); s = fmaf(v.w,w6.w,s);
                v = xv[7]; s = fmaf(v.x,w7.x,s); s = fmaf(v.y,w7.y,s); s = fmaf(v.z,w7.z,s); s = fmaf(v.w,w7.w,s);
                r = fmaxf(s, 0.f) * w2j;
            }
            r += __shfl_xor_sync(0xffffffffu, r, 8);
            r += __shfl_xor_sync(0xffffffffu, r, 4);
            r += __shfl_xor_sync(0xffffffffu, r, 2);
            r += __shfl_xor_sync(0xffffffffu, r, 1);
            if (valid && j == 0) {
                float a = r + b20;
                as_[p] = a;
                sa  += a;
                sa2  = fmaf(a, a, sa2);
            }
        }
        __syncthreads();

        // ---- Phase B: channel-split accumulation (x rows hot in L1) ----
        for (int p = pg; p < tn; p += 8) {
            float a  = as_[p];
            float xv = x[(size_t)(ts + p) * C_IN + c];
            axa = fmaf(xv, a, axa);
            ax += xv;
        }
        __syncthreads();
    }

    // ---- block reduction + global atomics ----
    r_axa[pg * C_IN + c] = axa;
    r_ax [pg * C_IN + c] = ax;
    if (j == 0) { r_sa[pl] = sa; r_sa2[pl] = sa2; }
    __syncthreads();
    if (tid < C_IN) {
        float A = 0.f, X = 0.f;
#pragma unroll
        for (int g = 0; g < 8; g++) { A += r_axa[g * C_IN + tid]; X += r_ax[g * C_IN + tid]; }
        atomicAdd(&g_seg_xa[seg][tid], A);
        atomicAdd(&g_seg_x [seg][tid], X);
    } else if (tid == C_IN) {
        float S = 0.f;
#pragma unroll
        for (int k = 0; k < 16; k++) S += r_sa[k];
        atomicAdd(&g_sum_a, S);
    } else if (tid == C_IN + 1) {
        float S = 0.f;
#pragma unroll
        for (int k = 0; k < 16; k++) S += r_sa2[k];
        atomicAdd(&g_sum_a2, S);
    }

    // ---- last block: BN2 affine + per-segment L2 normalize ----
    __threadfence();
    __syncthreads();
    if (tid == 0) sLast = (atomicAdd(&g_tick2, 1u) == (unsigned)(gridDim.x - 1));
    __syncthreads();
    if (sLast) {
        float m     = g_sum_a  * (1.f / N_PTS);
        float v     = g_sum_a2 * (1.f / N_PTS) - m * m;
        float alpha = rsqrtf(v + EPS_BN) * gamma2[0];
        float betaC = beta2[0] - m * alpha;
        int w = tid >> 5;                        // warp 0..7
#pragma unroll
        for (int half = 0; half < 2; half++) {
            int b = w + half * 8;
            float cnt = (float)length[b];
            float val = (alpha * g_seg_xa[b][c] + betaC * g_seg_x[b][c]) / cnt;
            float sq = val * val;
#pragma unroll
            for (int o = 16; o > 0; o >>= 1) sq += __shfl_xor_sync(0xffffffffu, sq, o);
            out[b * C_IN + c] = val / fmaxf(sqrtf(sq), EPS_NRM);
        }
    }
}

// ---------------------------------------------------------------- launch --
extern "C" void kernel_launch(void* const* d_in, const int* in_sizes, int n_in,
                              void* d_out, int out_size) {
    const float* x      = (const float*)d_in[0];
    const float* W1     = (const float*)d_in[1];
    const float* b1     = (const float*)d_in[2];
    const float* gamma1 = (const float*)d_in[3];
    const float* beta1  = (const float*)d_in[4];
    const float* W2     = (const float*)d_in[5];
    const float* b2     = (const float*)d_in[6];
    const float* gamma2 = (const float*)d_in[7];
    const float* beta2  = (const float*)d_in[8];
    const int* length   = (const int*)d_in[10];
    float* out          = (float*)d_out;

    zero_kernel<<<1, 256>>>();
    pass1_kernel<<<GRID1, 256>>>(x, W1, b1, gamma1, beta1);
    pass2_kernel<<<GRID2, 256>>>(x, W2, b2, gamma2, beta2, length, out);
}

// round 6
// speedup vs baseline: 1.1941x; 1.1941x over previous
#include <cuda_runtime.h>

#define N_PTS   800000
#define B_SEG   16
#define PTS     50000
#define C_IN    32
#define C_HID   16
#define EPS_BN  1e-5f
#define EPS_NRM 1e-12f

#define GRID1   592
#define CHUNK1  ((N_PTS + GRID1 - 1) / GRID1)   // 1352

#define BPS     37                               // blocks per segment, pass2
#define GRID2   (B_SEG * BPS)                    // 592 = 4 waves of 148
#define CHUNK2  ((PTS + BPS - 1) / BPS)          // 1352

// ---------------- device scratch (allocation-free; zeroed every launch) ----
__device__ float g_sum_h [C_HID];
__device__ float g_sum_h2[C_HID];
__device__ float g_W1f   [C_HID * C_IN];
__device__ float g_b1f   [C_HID];
__device__ float g_sum_a;
__device__ float g_sum_a2;
__device__ float g_seg_xa[B_SEG][C_IN];
__device__ float g_seg_x [B_SEG][C_IN];
__device__ unsigned g_tick1, g_tick2;

// ---------------------------------------------------------------- zero ----
__global__ void zero_kernel() {
    int t = threadIdx.x;
    for (int i = t; i < C_HID; i += blockDim.x) { g_sum_h[i] = 0.f; g_sum_h2[i] = 0.f; }
    if (t == 0) { g_sum_a = 0.f; g_sum_a2 = 0.f; g_tick1 = 0u; g_tick2 = 0u; }
    for (int i = t; i < B_SEG * C_IN; i += blockDim.x) {
        ((float*)g_seg_xa)[i] = 0.f;
        ((float*)g_seg_x )[i] = 0.f;
    }
}

// -------------------- pass1: Sum h, Sum h^2, then fold BN1 (last block) ----
// warp = 16 channels (j) x 2 half-rows (h). One point per warp-iteration.
// Thread holds 16 W coefficients (4 float4). 4 LDG.128 per point, no LDS.
__global__ void __launch_bounds__(256)
pass1_kernel(const float* __restrict__ x,
             const float* __restrict__ W1,
             const float* __restrict__ b1,
             const float* __restrict__ gamma1,
             const float* __restrict__ beta1) {
    __shared__ float red1[8 * C_HID];
    __shared__ float red2[8 * C_HID];
    __shared__ bool  sLast;
    int tid  = threadIdx.x;
    int lane = tid & 31;
    int w    = tid >> 5;          // warp 0..7
    int j    = lane & 15;         // hidden channel
    int h    = lane >> 4;         // half-row 0/1

    const float4* wp = (const float4*)(W1 + j * C_IN + h * 16);
    float4 w0 = wp[0], w1 = wp[1], w2 = wp[2], w3 = wp[3];
    float  bj = (h == 0) ? b1[j] : 0.f;

    int start = blockIdx.x * CHUNK1;
    int end   = min(N_PTS, start + CHUNK1);

    float sh = 0.f, sh2 = 0.f;
#pragma unroll 2
    for (int i = start + w; i < end; i += 8) {
        const float4* xv = (const float4*)(x + (size_t)i * C_IN + h * 16);
        float s = bj;
        float4 v;
        v = xv[0]; s = fmaf(v.x,w0.x,s); s = fmaf(v.y,w0.y,s); s = fmaf(v.z,w0.z,s); s = fmaf(v.w,w0.w,s);
        v = xv[1]; s = fmaf(v.x,w1.x,s); s = fmaf(v.y,w1.y,s); s = fmaf(v.z,w1.z,s); s = fmaf(v.w,w1.w,s);
        v = xv[2]; s = fmaf(v.x,w2.x,s); s = fmaf(v.y,w2.y,s); s = fmaf(v.z,w2.z,s); s = fmaf(v.w,w2.w,s);
        v = xv[3]; s = fmaf(v.x,w3.x,s); s = fmaf(v.y,w3.y,s); s = fmaf(v.z,w3.z,s); s = fmaf(v.w,w3.w,s);
        // combine half-rows: full s_j in all lanes (warp-uniform trip count)
        s += __shfl_xor_sync(0xffffffffu, s, 16);
        sh  += s;
        sh2  = fmaf(s, s, sh2);
    }

    if (h == 0) { red1[w * 16 + j] = sh; red2[w * 16 + j] = sh2; }
    __syncthreads();
    if (tid < C_HID) {
        float a = 0.f, b = 0.f;
#pragma unroll
        for (int ww = 0; ww < 8; ww++) { a += red1[ww * 16 + tid]; b += red2[ww * 16 + tid]; }
        atomicAdd(&g_sum_h [tid], a);
        atomicAdd(&g_sum_h2[tid], b);
    }

    // ---- last block folds BN1 into W1', b1' ----
    __threadfence();
    __syncthreads();
    if (tid == 0) sLast = (atomicAdd(&g_tick1, 1u) == (unsigned)(gridDim.x - 1));
    __syncthreads();
    if (sLast) {
        __shared__ float sInv[C_HID];
        if (tid < C_HID) {
            float m   = g_sum_h [tid] * (1.f / N_PTS);
            float vv  = g_sum_h2[tid] * (1.f / N_PTS) - m * m;
            float inv = rsqrtf(vv + EPS_BN) * gamma1[tid];
            sInv[tid] = inv;
            g_b1f[tid] = (b1[tid] - m) * inv + beta1[tid];
        }
        __syncthreads();
        for (int idx = tid; idx < C_HID * C_IN; idx += 256)
            g_W1f[idx] = W1[idx] * sInv[idx >> 5];
    }
}

// ---- pass2: fused attention + accumulation, finalize in last block --------
// Same warp layout. After the j-reduce every lane holds `a`; lane L then
// accumulates channel L via one coalesced scalar LDG (L1-hit on same line).
__global__ void __launch_bounds__(256)
pass2_kernel(const float* __restrict__ x,
             const float* __restrict__ W2,
             const float* __restrict__ b2,
             const float* __restrict__ gamma2,
             const float* __restrict__ beta2,
             const int*   __restrict__ length,
             float*       __restrict__ out) {
    __shared__ float r_axa[8][C_IN];
    __shared__ float r_ax [8][C_IN];
    __shared__ float r_sa [8];
    __shared__ float r_sa2[8];
    __shared__ bool  sLast;
    int tid  = threadIdx.x;
    int lane = tid & 31;
    int w    = tid >> 5;
    int j    = lane & 15;
    int h    = lane >> 4;

    const float4* wp = (const float4*)(g_W1f + j * C_IN + h * 16);
    float4 w0 = wp[0], w1 = wp[1], w2 = wp[2], w3 = wp[3];
    float  bj  = (h == 0) ? g_b1f[j] : 0.f;
    float  w2j = W2[j];
    float  b20 = b2[0];

    int seg   = blockIdx.x / BPS;
    int blk   = blockIdx.x % BPS;
    int start = seg * PTS + blk * CHUNK2;
    int end   = min(seg * PTS + PTS, start + CHUNK2);

    float sa = 0.f, sa2 = 0.f, axa = 0.f, ax = 0.f;

#pragma unroll 2
    for (int i = start + w; i < end; i += 8) {
        const float*  row = x + (size_t)i * C_IN;
        const float4* xv  = (const float4*)(row + h * 16);
        float s = bj;
        float4 v;
        v = xv[0]; s = fmaf(v.x,w0.x,s); s = fmaf(v.y,w0.y,s); s = fmaf(v.z,w0.z,s); s = fmaf(v.w,w0.w,s);
        v = xv[1]; s = fmaf(v.x,w1.x,s); s = fmaf(v.y,w1.y,s); s = fmaf(v.z,w1.z,s); s = fmaf(v.w,w1.w,s);
        v = xv[2]; s = fmaf(v.x,w2.x,s); s = fmaf(v.y,w2.y,s); s = fmaf(v.z,w2.z,s); s = fmaf(v.w,w2.w,s);
        v = xv[3]; s = fmaf(v.x,w3.x,s); s = fmaf(v.y,w3.y,s); s = fmaf(v.z,w3.z,s); s = fmaf(v.w,w3.w,s);
        s += __shfl_xor_sync(0xffffffffu, s, 16);      // full s_j
        float r = fmaxf(s, 0.f) * w2j;                  // relu per channel
        r += __shfl_xor_sync(0xffffffffu, r, 8);        // reduce over j
        r += __shfl_xor_sync(0xffffffffu, r, 4);
        r += __shfl_xor_sync(0xffffffffu, r, 2);
        r += __shfl_xor_sync(0xffffffffu, r, 1);
        float a  = r + b20;                             // a_pre in ALL lanes
        float xl = row[lane];                           // coalesced, L1-hit
        axa = fmaf(xl, a, axa);
        ax += xl;
        if (lane == 0) { sa += a; sa2 = fmaf(a, a, sa2); }
    }

    // ---- block reduction + global atomics ----
    r_axa[w][lane] = axa;
    r_ax [w][lane] = ax;
    if (lane == 0) { r_sa[w] = sa; r_sa2[w] = sa2; }
    __syncthreads();
    if (tid < C_IN) {
        float A = 0.f, X = 0.f;
#pragma unroll
        for (int g = 0; g < 8; g++) { A += r_axa[g][tid]; X += r_ax[g][tid]; }
        atomicAdd(&g_seg_xa[seg][tid], A);
        atomicAdd(&g_seg_x [seg][tid], X);
    } else if (tid == C_IN) {
        float S = 0.f;
#pragma unroll
        for (int k = 0; k < 8; k++) S += r_sa[k];
        atomicAdd(&g_sum_a, S);
    } else if (tid == C_IN + 1) {
        float S = 0.f;
#pragma unroll
        for (int k = 0; k < 8; k++) S += r_sa2[k];
        atomicAdd(&g_sum_a2, S);
    }

    // ---- last block: BN2 affine + per-segment L2 normalize ----
    __threadfence();
    __syncthreads();
    if (tid == 0) sLast = (atomicAdd(&g_tick2, 1u) == (unsigned)(gridDim.x - 1));
    __syncthreads();
    if (sLast) {
        float m     = g_sum_a  * (1.f / N_PTS);
        float v     = g_sum_a2 * (1.f / N_PTS) - m * m;
        float alpha = rsqrtf(v + EPS_BN) * gamma2[0];
        float betaC = beta2[0] - m * alpha;
#pragma unroll
        for (int half = 0; half < 2; half++) {
            int b = w + half * 8;
            float cnt = (float)length[b];
            float val = (alpha * g_seg_xa[b][lane] + betaC * g_seg_x[b][lane]) / cnt;
            float sq = val * val;
#pragma unroll
            for (int o = 16; o > 0; o >>= 1) sq += __shfl_xor_sync(0xffffffffu, sq, o);
            out[b * C_IN + lane] = val / fmaxf(sqrtf(sq), EPS_NRM);
        }
    }
}

// ---------------------------------------------------------------- launch --
extern "C" void kernel_launch(void* const* d_in, const int* in_sizes, int n_in,
                              void* d_out, int out_size) {
    const float* x      = (const float*)d_in[0];
    const float* W1     = (const float*)d_in[1];
    const float* b1     = (const float*)d_in[2];
    const float* gamma1 = (const float*)d_in[3];
    const float* beta1  = (const float*)d_in[4];
    const float* W2     = (const float*)d_in[5];
    const float* b2     = (const float*)d_in[6];
    const float* gamma2 = (const float*)d_in[7];
    const float* beta2  = (const float*)d_in[8];
    const int* length   = (const int*)d_in[10];
    float* out          = (float*)d_out;

    zero_kernel<<<1, 256>>>();
    pass1_kernel<<<GRID1, 256>>>(x, W1, b1, gamma1, beta1);
    pass2_kernel<<<GRID2, 256>>>(x, W2, b2, gamma2, beta2, length, out);
}

// round 7
// speedup vs baseline: 1.2160x; 1.0183x over previous
#include <cuda_runtime.h>

#define N_PTS   800000
#define B_SEG   16
#define PTS     50000
#define C_IN    32
#define C_HID   16
#define EPS_BN  1e-5f
#define EPS_NRM 1e-12f

#define GRID1   888                              // 6 blocks/SM on 148 SMs
#define CHUNK1  ((N_PTS + GRID1 - 1) / GRID1)    // 901

#define BPS     55                               // blocks per segment, pass2
#define GRID2   (B_SEG * BPS)                    // 880
#define CHUNK2  ((PTS + BPS - 1) / BPS)          // 910

// ---------------- device scratch (zero-init at load; self-reset each run) --
__device__ float g_sum_h [C_HID];
__device__ float g_sum_h2[C_HID];
__device__ float g_W1f   [C_HID * C_IN];
__device__ float g_b1f   [C_HID];
__device__ float g_sum_a;
__device__ float g_sum_a2;
__device__ float g_seg_xa[B_SEG][C_IN];
__device__ float g_seg_x [B_SEG][C_IN];
__device__ unsigned g_tick1, g_tick2;

// -------------------- pass1: Sum h, Sum h^2, then fold BN1 (last block) ----
// warp = 16 channels (j) x 2 half-rows (h). One point per warp-iteration.
__global__ void __launch_bounds__(256, 6)
pass1_kernel(const float* __restrict__ x,
             const float* __restrict__ W1,
             const float* __restrict__ b1,
             const float* __restrict__ gamma1,
             const float* __restrict__ beta1) {
    __shared__ float red1[8 * C_HID];
    __shared__ float red2[8 * C_HID];
    __shared__ bool  sLast;
    int tid  = threadIdx.x;
    int lane = tid & 31;
    int w    = tid >> 5;          // warp 0..7
    int j    = lane & 15;         // hidden channel
    int h    = lane >> 4;         // half-row 0/1

    const float4* wp = (const float4*)(W1 + j * C_IN + h * 16);
    float4 w0 = wp[0], w1 = wp[1], w2 = wp[2], w3 = wp[3];
    float  bj = (h == 0) ? b1[j] : 0.f;

    int start = blockIdx.x * CHUNK1;
    int end   = min(N_PTS, start + CHUNK1);

    float sh = 0.f, sh2 = 0.f;
#pragma unroll 2
    for (int i = start + w; i < end; i += 8) {
        const float4* xv = (const float4*)(x + (size_t)i * C_IN + h * 16);
        float4 v;
        float s0 = bj, s1 = 0.f;
        v = xv[0]; s0 = fmaf(v.x,w0.x,s0); s0 = fmaf(v.y,w0.y,s0); s0 = fmaf(v.z,w0.z,s0); s0 = fmaf(v.w,w0.w,s0);
        v = xv[1]; s1 = fmaf(v.x,w1.x,s1); s1 = fmaf(v.y,w1.y,s1); s1 = fmaf(v.z,w1.z,s1); s1 = fmaf(v.w,w1.w,s1);
        v = xv[2]; s0 = fmaf(v.x,w2.x,s0); s0 = fmaf(v.y,w2.y,s0); s0 = fmaf(v.z,w2.z,s0); s0 = fmaf(v.w,w2.w,s0);
        v = xv[3]; s1 = fmaf(v.x,w3.x,s1); s1 = fmaf(v.y,w3.y,s1); s1 = fmaf(v.z,w3.z,s1); s1 = fmaf(v.w,w3.w,s1);
        float s = s0 + s1;
        s += __shfl_xor_sync(0xffffffffu, s, 16);   // combine half-rows
        sh  += s;
        sh2  = fmaf(s, s, sh2);
    }

    if (h == 0) { red1[w * 16 + j] = sh; red2[w * 16 + j] = sh2; }
    __syncthreads();
    if (tid < C_HID) {
        float a = 0.f, b = 0.f;
#pragma unroll
        for (int ww = 0; ww < 8; ww++) { a += red1[ww * 16 + tid]; b += red2[ww * 16 + tid]; }
        atomicAdd(&g_sum_h [tid], a);
        atomicAdd(&g_sum_h2[tid], b);
    }

    // ---- last block: fold BN1 into W1', b1'; then self-reset scratch ----
    __threadfence();
    __syncthreads();
    if (tid == 0) sLast = (atomicAdd(&g_tick1, 1u) == (unsigned)(gridDim.x - 1));
    __syncthreads();
    if (sLast) {
        __shared__ float sInv[C_HID];
        if (tid < C_HID) {
            float m   = g_sum_h [tid] * (1.f / N_PTS);
            float vv  = g_sum_h2[tid] * (1.f / N_PTS) - m * m;
            float inv = rsqrtf(vv + EPS_BN) * gamma1[tid];
            sInv[tid] = inv;
            g_b1f[tid] = (b1[tid] - m) * inv + beta1[tid];
        }
        __syncthreads();
        for (int idx = tid; idx < C_HID * C_IN; idx += 256)
            g_W1f[idx] = W1[idx] * sInv[idx >> 5];
        // reset for next graph replay (values consumed above)
        if (tid < C_HID) { g_sum_h[tid] = 0.f; g_sum_h2[tid] = 0.f; }
        if (tid == 0)    g_tick1 = 0u;
    }
}

// ---- pass2: fused attention + accumulation, finalize + reset (last block) -
__global__ void __launch_bounds__(256, 6)
pass2_kernel(const float* __restrict__ x,
             const float* __restrict__ W2,
             const float* __restrict__ b2,
             const float* __restrict__ gamma2,
             const float* __restrict__ beta2,
             const int*   __restrict__ length,
             float*       __restrict__ out) {
    __shared__ float r_axa[8][C_IN];
    __shared__ float r_ax [8][C_IN];
    __shared__ float r_sa [8];
    __shared__ float r_sa2[8];
    __shared__ bool  sLast;
    int tid  = threadIdx.x;
    int lane = tid & 31;
    int w    = tid >> 5;
    int j    = lane & 15;
    int h    = lane >> 4;

    const float4* wp = (const float4*)(g_W1f + j * C_IN + h * 16);
    float4 w0 = wp[0], w1 = wp[1], w2 = wp[2], w3 = wp[3];
    float  bj  = (h == 0) ? g_b1f[j] : 0.f;
    float  w2j = W2[j];
    float  b20 = b2[0];

    int seg   = blockIdx.x / BPS;
    int blk   = blockIdx.x % BPS;
    int start = seg * PTS + blk * CHUNK2;
    int end   = min(seg * PTS + PTS, start + CHUNK2);

    float sa = 0.f, sa2 = 0.f, axa = 0.f, ax = 0.f;

#pragma unroll 2
    for (int i = start + w; i < end; i += 8) {
        const float*  row = x + (size_t)i * C_IN;
        const float4* xv  = (const float4*)(row + h * 16);
        float4 v;
        float s0 = bj, s1 = 0.f;
        v = xv[0]; s0 = fmaf(v.x,w0.x,s0); s0 = fmaf(v.y,w0.y,s0); s0 = fmaf(v.z,w0.z,s0); s0 = fmaf(v.w,w0.w,s0);
        v = xv[1]; s1 = fmaf(v.x,w1.x,s1); s1 = fmaf(v.y,w1.y,s1); s1 = fmaf(v.z,w1.z,s1); s1 = fmaf(v.w,w1.w,s1);
        v = xv[2]; s0 = fmaf(v.x,w2.x,s0); s0 = fmaf(v.y,w2.y,s0); s0 = fmaf(v.z,w2.z,s0); s0 = fmaf(v.w,w2.w,s0);
        v = xv[3]; s1 = fmaf(v.x,w3.x,s1); s1 = fmaf(v.y,w3.y,s1); s1 = fmaf(v.z,w3.z,s1); s1 = fmaf(v.w,w3.w,s1);
        float s = s0 + s1;
        s += __shfl_xor_sync(0xffffffffu, s, 16);      // full s_j
        float r = fmaxf(s, 0.f) * w2j;                  // relu per channel
        r += __shfl_xor_sync(0xffffffffu, r, 8);        // reduce over j
        r += __shfl_xor_sync(0xffffffffu, r, 4);
        r += __shfl_xor_sync(0xffffffffu, r, 2);
        r += __shfl_xor_sync(0xffffffffu, r, 1);
        float a  = r + b20;                             // a_pre in ALL lanes
        float xl = row[lane];                           // coalesced, L1-hit
        axa = fmaf(xl, a, axa);
        ax += xl;
        if (lane == 0) { sa += a; sa2 = fmaf(a, a, sa2); }
    }

    // ---- block reduction + global atomics ----
    r_axa[w][lane] = axa;
    r_ax [w][lane] = ax;
    if (lane == 0) { r_sa[w] = sa; r_sa2[w] = sa2; }
    __syncthreads();
    if (tid < C_IN) {
        float A = 0.f, X = 0.f;
#pragma unroll
        for (int g = 0; g < 8; g++) { A += r_axa[g][tid]; X += r_ax[g][tid]; }
        atomicAdd(&g_seg_xa[seg][tid], A);
        atomicAdd(&g_seg_x [seg][tid], X);
    } else if (tid == C_IN) {
        float S = 0.f;
#pragma unroll
        for (int k = 0; k < 8; k++) S += r_sa[k];
        atomicAdd(&g_sum_a, S);
    } else if (tid == C_IN + 1) {
        float S = 0.f;
#pragma unroll
        for (int k = 0; k < 8; k++) S += r_sa2[k];
        atomicAdd(&g_sum_a2, S);
    }

    // ---- last block: BN2 affine + L2 normalize; then self-reset scratch ---
    __threadfence();
    __syncthreads();
    if (tid == 0) sLast = (atomicAdd(&g_tick2, 1u) == (unsigned)(gridDim.x - 1));
    __syncthreads();
    if (sLast) {
        float m     = g_sum_a  * (1.f / N_PTS);
        float v     = g_sum_a2 * (1.f / N_PTS) - m * m;
        float alpha = rsqrtf(v + EPS_BN) * gamma2[0];
        float betaC = beta2[0] - m * alpha;
#pragma unroll
        for (int half = 0; half < 2; half++) {
            int b = w + half * 8;
            float cnt = (float)length[b];
            float val = (alpha * g_seg_xa[b][lane] + betaC * g_seg_x[b][lane]) / cnt;
            float sq = val * val;
#pragma unroll
            for (int o = 16; o > 0; o >>= 1) sq += __shfl_xor_sync(0xffffffffu, sq, o);
            out[b * C_IN + lane] = val / fmaxf(sqrtf(sq), EPS_NRM);
        }
        __syncthreads();
        // reset for next graph replay (all values consumed above)
        for (int i2 = tid; i2 < B_SEG * C_IN; i2 += 256) {
            ((float*)g_seg_xa)[i2] = 0.f;
            ((float*)g_seg_x )[i2] = 0.f;
        }
        if (tid == 0) { g_sum_a = 0.f; g_sum_a2 = 0.f; g_tick2 = 0u; }
    }
}

// ---------------------------------------------------------------- launch --
extern "C" void kernel_launch(void* const* d_in, const int* in_sizes, int n_in,
                              void* d_out, int out_size) {
    const float* x      = (const float*)d_in[0];
    const float* W1     = (const float*)d_in[1];
    const float* b1     = (const float*)d_in[2];
    const float* gamma1 = (const float*)d_in[3];
    const float* beta1  = (const float*)d_in[4];
    const float* W2     = (const float*)d_in[5];
    const float* b2     = (const float*)d_in[6];
    const float* gamma2 = (const float*)d_in[7];
    const float* beta2  = (const float*)d_in[8];
    const int* length   = (const int*)d_in[10];
    float* out          = (float*)d_out;

    pass1_kernel<<<GRID1, 256>>>(x, W1, b1, gamma1, beta1);
    pass2_kernel<<<GRID2, 256>>>(x, W2, b2, gamma2, beta2, length, out);
}

// round 9
// speedup vs baseline: 1.5510x; 1.2755x over previous
#include <cuda_runtime.h>

#define N_PTS   800000
#define B_SEG   16
#define PTS     50000
#define C_IN    32
#define C_HID   16
#define EPS_BN  1e-5f
#define EPS_NRM 1e-12f

#define GRID1   740                              // 5 blocks/SM on 148 SMs
#define CHUNK1  ((N_PTS + GRID1 - 1) / GRID1)    // 1082

#define BPS     46                               // blocks per segment, pass2
#define GRID2   (B_SEG * BPS)                    // 736
#define CHUNK2  1088                             // even; 45*1088+1040=50000

// ---------------- device scratch (zero-init at load; self-reset each run) --
__device__ float g_sum_h [C_HID];
__device__ float g_sum_h2[C_HID];
__device__ float g_W1f   [C_HID * C_IN];
__device__ float g_b1f   [C_HID];
__device__ float g_sum_a;
__device__ float g_sum_a2;
__device__ float g_seg_xa[B_SEG][C_IN];
__device__ float g_seg_x [B_SEG][C_IN];
__device__ unsigned g_tick1, g_tick2;

// -------------------- pass1: Sum h, Sum h^2, then fold BN1 (last block) ----
// warp = 16 channels (j) x 2 half-rows (h). One point per warp-iteration.
__global__ void __launch_bounds__(256, 5)
pass1_kernel(const float* __restrict__ x,
             const float* __restrict__ W1,
             const float* __restrict__ b1,
             const float* __restrict__ gamma1,
             const float* __restrict__ beta1) {
    __shared__ float red1[8 * C_HID];
    __shared__ float red2[8 * C_HID];
    __shared__ bool  sLast;
    int tid  = threadIdx.x;
    int lane = tid & 31;
    int w    = tid >> 5;          // warp 0..7
    int j    = lane & 15;         // hidden channel
    int h    = lane >> 4;         // half-row 0/1

    const float4* wp = (const float4*)(W1 + j * C_IN + h * 16);
    float4 w0 = wp[0], w1 = wp[1], w2 = wp[2], w3 = wp[3];
    float  bj = (h == 0) ? b1[j] : 0.f;

    int start = blockIdx.x * CHUNK1;
    int end   = min(N_PTS, start + CHUNK1);

    float sh = 0.f, sh2 = 0.f;
#pragma unroll 4
    for (int i = start + w; i < end; i += 8) {
        const float4* xv = (const float4*)(x + (size_t)i * C_IN + h * 16);
        float4 v;
        float s0 = bj, s1 = 0.f;
        v = xv[0]; s0 = fmaf(v.x,w0.x,s0); s0 = fmaf(v.y,w0.y,s0); s0 = fmaf(v.z,w0.z,s0); s0 = fmaf(v.w,w0.w,s0);
        v = xv[1]; s1 = fmaf(v.x,w1.x,s1); s1 = fmaf(v.y,w1.y,s1); s1 = fmaf(v.z,w1.z,s1); s1 = fmaf(v.w,w1.w,s1);
        v = xv[2]; s0 = fmaf(v.x,w2.x,s0); s0 = fmaf(v.y,w2.y,s0); s0 = fmaf(v.z,w2.z,s0); s0 = fmaf(v.w,w2.w,s0);
        v = xv[3]; s1 = fmaf(v.x,w3.x,s1); s1 = fmaf(v.y,w3.y,s1); s1 = fmaf(v.z,w3.z,s1); s1 = fmaf(v.w,w3.w,s1);
        float s = s0 + s1;
        s += __shfl_xor_sync(0xffffffffu, s, 16);   // combine half-rows
        sh  += s;
        sh2  = fmaf(s, s, sh2);
    }

    if (h == 0) { red1[w * 16 + j] = sh; red2[w * 16 + j] = sh2; }
    __syncthreads();
    if (tid < C_HID) {
        float a = 0.f, b = 0.f;
#pragma unroll
        for (int ww = 0; ww < 8; ww++) { a += red1[ww * 16 + tid]; b += red2[ww * 16 + tid]; }
        atomicAdd(&g_sum_h [tid], a);
        atomicAdd(&g_sum_h2[tid], b);
    }

    // ---- last block: fold BN1 into W1', b1'; then self-reset scratch ----
    __threadfence();
    __syncthreads();
    if (tid == 0) sLast = (atomicAdd(&g_tick1, 1u) == (unsigned)(gridDim.x - 1));
    __syncthreads();
    if (sLast) {
        __shared__ float sInv[C_HID];
        if (tid < C_HID) {
            float m   = g_sum_h [tid] * (1.f / N_PTS);
            float vv  = g_sum_h2[tid] * (1.f / N_PTS) - m * m;
            float inv = rsqrtf(vv + EPS_BN) * gamma1[tid];
            sInv[tid] = inv;
            g_b1f[tid] = (b1[tid] - m) * inv + beta1[tid];
        }
        __syncthreads();
        for (int idx = tid; idx < C_HID * C_IN; idx += 256)
            g_W1f[idx] = W1[idx] * sInv[idx >> 5];
        // reset for next graph replay (values consumed above)
        if (tid < C_HID) { g_sum_h[tid] = 0.f; g_sum_h2[tid] = 0.f; }
        if (tid == 0)    g_tick1 = 0u;
    }
}

// ---- pass2: fused attention + accumulation, PAIRED points per warp-iter ---
// The j-reduce (xor 8,4,2,1) operates within each 16-lane half, so placing
// point0's r in half h=0 and point1's in half h=1 reduces both at once.
__global__ void __launch_bounds__(256, 5)
pass2_kernel(const float* __restrict__ x,
             const float* __restrict__ W2,
             const float* __restrict__ b2,
             const float* __restrict__ gamma2,
             const float* __restrict__ beta2,
             const int*   __restrict__ length,
             float*       __restrict__ out) {
    __shared__ float r_axa[8][C_IN];
    __shared__ float r_ax [8][C_IN];
    __shared__ float r_sa [8];
    __shared__ float r_sa2[8];
    __shared__ bool  sLast;
    int tid  = threadIdx.x;
    int lane = tid & 31;
    int w    = tid >> 5;
    int j    = lane & 15;
    int h    = lane >> 4;

    const float4* wp = (const float4*)(g_W1f + j * C_IN + h * 16);
    float4 w0 = wp[0], w1 = wp[1], w2 = wp[2], w3 = wp[3];
    float  bj  = (h == 0) ? g_b1f[j] : 0.f;
    float  w2j = W2[j];
    float  b20 = b2[0];

    int seg   = blockIdx.x / BPS;
    int blk   = blockIdx.x % BPS;
    int start = seg * PTS + blk * CHUNK2;
    int end   = min(seg * PTS + PTS, start + CHUNK2);
    // (end - start) is always even -> pairs never straddle

    float sa = 0.f, sa2 = 0.f, axa = 0.f, ax = 0.f;

#pragma unroll 2
    for (int i = start + 2 * w; i < end; i += 16) {
        const float*  row0 = x + (size_t)i * C_IN;
        const float*  row1 = row0 + C_IN;
        const float4* xv0  = (const float4*)(row0 + h * 16);
        const float4* xv1  = (const float4*)(row1 + h * 16);
        float4 v;
        float p0a = bj, p0b = 0.f, p1a = bj, p1b = 0.f;
        v = xv0[0]; p0a = fmaf(v.x,w0.x,p0a); p0a = fmaf(v.y,w0.y,p0a); p0a = fmaf(v.z,w0.z,p0a); p0a = fmaf(v.w,w0.w,p0a);
        v = xv0[1]; p0b = fmaf(v.x,w1.x,p0b); p0b = fmaf(v.y,w1.y,p0b); p0b = fmaf(v.z,w1.z,p0b); p0b = fmaf(v.w,w1.w,p0b);
        v = xv0[2]; p0a = fmaf(v.x,w2.x,p0a); p0a = fmaf(v.y,w2.y,p0a); p0a = fmaf(v.z,w2.z,p0a); p0a = fmaf(v.w,w2.w,p0a);
        v = xv0[3]; p0b = fmaf(v.x,w3.x,p0b); p0b = fmaf(v.y,w3.y,p0b); p0b = fmaf(v.z,w3.z,p0b); p0b = fmaf(v.w,w3.w,p0b);
        v = xv1[0]; p1a = fmaf(v.x,w0.x,p1a); p1a = fmaf(v.y,w0.y,p1a); p1a = fmaf(v.z,w0.z,p1a); p1a = fmaf(v.w,w0.w,p1a);
        v = xv1[1]; p1b = fmaf(v.x,w1.x,p1b); p1b = fmaf(v.y,w1.y,p1b); p1b = fmaf(v.z,w1.z,p1b); p1b = fmaf(v.w,w1.w,p1b);
        v = xv1[2]; p1a = fmaf(v.x,w2.x,p1a); p1a = fmaf(v.y,w2.y,p1a); p1a = fmaf(v.z,w2.z,p1a); p1a = fmaf(v.w,w2.w,p1a);
        v = xv1[3]; p1b = fmaf(v.x,w3.x,p1b); p1b = fmaf(v.y,w3.y,p1b); p1b = fmaf(v.z,w3.z,p1b); p1b = fmaf(v.w,w3.w,p1b);
        float s0 = p0a + p0b;
        float s1 = p1a + p1b;
        s0 += __shfl_xor_sync(0xffffffffu, s0, 16);   // full s_j, point 0
        s1 += __shfl_xor_sync(0xffffffffu, s1, 16);   // full s_j, point 1
        float r0 = fmaxf(s0, 0.f) * w2j;
        float r1 = fmaxf(s1, 0.f) * w2j;
        float t  = (h == 0) ? r0 : r1;                // both reductions at once
        t += __shfl_xor_sync(0xffffffffu, t, 8);
        t += __shfl_xor_sync(0xffffffffu, t, 4);
        t += __shfl_xor_sync(0xffffffffu, t, 2);
        t += __shfl_xor_sync(0xffffffffu, t, 1);
        float other = __shfl_xor_sync(0xffffffffu, t, 16);
        float a0 = ((h == 0) ? t : other) + b20;
        float a1 = ((h == 0) ? other : t) + b20;
        float xl0 = row0[lane];                       // coalesced, L1-hit
        float xl1 = row1[lane];
        axa = fmaf(xl0, a0, axa);
        axa = fmaf(xl1, a1, axa);
        ax += xl0 + xl1;
        if (lane == 0) {
            sa += a0 + a1;
            sa2 = fmaf(a0, a0, sa2);
            sa2 = fmaf(a1, a1, sa2);
        }
    }

    // ---- block reduction + global atomics ----
    r_axa[w][lane] = axa;
    r_ax [w][lane] = ax;
    if (lane == 0) { r_sa[w] = sa; r_sa2[w] = sa2; }
    __syncthreads();
    if (tid < C_IN) {
        float A = 0.f, X = 0.f;
#pragma unroll
        for (int g = 0; g < 8; g++) { A += r_axa[g][tid]; X += r_ax[g][tid]; }
        atomicAdd(&g_seg_xa[seg][tid], A);
        atomicAdd(&g_seg_x [seg][tid], X);
    } else if (tid == C_IN) {
        float S = 0.f;
#pragma unroll
        for (int k = 0; k < 8; k++) S += r_sa[k];
        atomicAdd(&g_sum_a, S);
    } else if (tid == C_IN + 1) {
        float S = 0.f;
#pragma unroll
        for (int k = 0; k < 8; k++) S += r_sa2[k];
        atomicAdd(&g_sum_a2, S);
    }

    // ---- last block: BN2 affine + L2 normalize; then self-reset scratch ---
    __threadfence();
    __syncthreads();
    if (tid == 0) sLast = (atomicAdd(&g_tick2, 1u) == (unsigned)(gridDim.x - 1));
    __syncthreads();
    if (sLast) {
        float m     = g_sum_a  * (1.f / N_PTS);
        float v     = g_sum_a2 * (1.f / N_PTS) - m * m;
        float alpha = rsqrtf(v + EPS_BN) * gamma2[0];
        float betaC = beta2[0] - m * alpha;
#pragma unroll
        for (int half = 0; half < 2; half++) {
            int b = w + half * 8;
            float cnt = (float)length[b];
            float val = (alpha * g_seg_xa[b][lane] + betaC * g_seg_x[b][lane]) / cnt;
            float sq = val * val;
#pragma unroll
            for (int o = 16; o > 0; o >>= 1) sq += __shfl_xor_sync(0xffffffffu, sq, o);
            out[b * C_IN + lane] = val / fmaxf(sqrtf(sq), EPS_NRM);
        }
        __syncthreads();
        // reset for next graph replay (all values consumed above)
        for (int i2 = tid; i2 < B_SEG * C_IN; i2 += 256) {
            ((float*)g_seg_xa)[i2] = 0.f;
            ((float*)g_seg_x )[i2] = 0.f;
        }
        if (tid == 0) { g_sum_a = 0.f; g_sum_a2 = 0.f; g_tick2 = 0u; }
    }
}

// ---------------------------------------------------------------- launch --
extern "C" void kernel_launch(void* const* d_in, const int* in_sizes, int n_in,
                              void* d_out, int out_size) {
    const float* x      = (const float*)d_in[0];
    const float* W1     = (const float*)d_in[1];
    const float* b1     = (const float*)d_in[2];
    const float* gamma1 = (const float*)d_in[3];
    const float* beta1  = (const float*)d_in[4];
    const float* W2     = (const float*)d_in[5];
    const float* b2     = (const float*)d_in[6];
    const float* gamma2 = (const float*)d_in[7];
    const float* beta2  = (const float*)d_in[8];
    const int* length   = (const int*)d_in[10];
    float* out          = (float*)d_out;

    pass1_kernel<<<GRID1, 256>>>(x, W1, b1, gamma1, beta1);
    pass2_kernel<<<GRID2, 256>>>(x, W2, b2, gamma2, beta2, length, out);
}

// round 11
// speedup vs baseline: 2.0738x; 1.3371x over previous
#include <cuda_runtime.h>

#define N_PTS   800000
#define B_SEG   16
#define PTS     50000
#define C_IN    32
#define C_HID   16
#define EPS_BN  1e-5f
#define EPS_NRM 1e-12f

#define TP      128                              // staged tile (points) = 16KB

#define GRID1   740                              // 5 blocks/SM on 148 SMs
#define CHUNK1  ((N_PTS + GRID1 - 1) / GRID1)    // 1082

#define BPS     46                               // blocks per segment, pass2
#define GRID2   (B_SEG * BPS)                    // 736
#define CHUNK2  1088                             // even; 45*1088+1040=50000

// ---------------- device scratch (zero-init at load; self-reset each run) --
__device__ float g_sum_h [C_HID];
__device__ float g_sum_h2[C_HID];
__device__ float g_W1f   [C_HID * C_IN];
__device__ float g_b1f   [C_HID];
__device__ float g_sum_a;
__device__ float g_sum_a2;
__device__ float g_seg_xa[B_SEG][C_IN];
__device__ float g_seg_x [B_SEG][C_IN];
__device__ unsigned g_tick1, g_tick2;

// -------------------- pass1: Sum h, Sum h^2, then fold BN1 (last block) ----
// Tile-stage x into smem (coalesced distinct-address LDG = 1 wf/row), then
// compute from smem where the 16-lane broadcast is free.
__global__ void __launch_bounds__(256, 5)
pass1_kernel(const float* __restrict__ x,
             const float* __restrict__ W1,
             const float* __restrict__ b1,
             const float* __restrict__ gamma1,
             const float* __restrict__ beta1) {
    __shared__ __align__(16) float4 sx[TP * 8];   // 16 KB tile
    __shared__ float red1[8 * C_HID];
    __shared__ float red2[8 * C_HID];
    __shared__ bool  sLast;
    int tid  = threadIdx.x;
    int lane = tid & 31;
    int w    = tid >> 5;          // warp 0..7
    int j    = lane & 15;         // hidden channel
    int h    = lane >> 4;         // half-row 0/1

    const float4* wp = (const float4*)(W1 + j * C_IN + h * 16);
    float4 w0 = wp[0], w1 = wp[1], w2 = wp[2], w3 = wp[3];
    float  bj = (h == 0) ? b1[j] : 0.f;

    int start = blockIdx.x * CHUNK1;
    int end   = min(N_PTS, start + CHUNK1);

    float sh = 0.f, sh2 = 0.f;
    for (int ts = start; ts < end; ts += TP) {
        int tn = min(TP, end - ts);
        // ---- stage tile (coalesced, distinct addresses) ----
        const float4* src = (const float4*)(x + (size_t)ts * C_IN);
        int nf = tn * 8;
        for (int f = tid; f < nf; f += 256) sx[f] = src[f];
        __syncthreads();
        // ---- compute from smem (broadcast free) ----
        for (int p = w; p < tn; p += 8) {          // warp-uniform trips
            const float4* xv = &sx[p * 8 + h * 4];
            float4 v;
            float s0 = bj, s1 = 0.f;
            v = xv[0]; s0 = fmaf(v.x,w0.x,s0); s0 = fmaf(v.y,w0.y,s0); s0 = fmaf(v.z,w0.z,s0); s0 = fmaf(v.w,w0.w,s0);
            v = xv[1]; s1 = fmaf(v.x,w1.x,s1); s1 = fmaf(v.y,w1.y,s1); s1 = fmaf(v.z,w1.z,s1); s1 = fmaf(v.w,w1.w,s1);
            v = xv[2]; s0 = fmaf(v.x,w2.x,s0); s0 = fmaf(v.y,w2.y,s0); s0 = fmaf(v.z,w2.z,s0); s0 = fmaf(v.w,w2.w,s0);
            v = xv[3]; s1 = fmaf(v.x,w3.x,s1); s1 = fmaf(v.y,w3.y,s1); s1 = fmaf(v.z,w3.z,s1); s1 = fmaf(v.w,w3.w,s1);
            float s = s0 + s1;
            s += __shfl_xor_sync(0xffffffffu, s, 16);   // combine half-rows
            sh  += s;
            sh2  = fmaf(s, s, sh2);
        }
        __syncthreads();
    }

    if (h == 0) { red1[w * 16 + j] = sh; red2[w * 16 + j] = sh2; }
    __syncthreads();
    if (tid < C_HID) {
        float a = 0.f, b = 0.f;
#pragma unroll
        for (int ww = 0; ww < 8; ww++) { a += red1[ww * 16 + tid]; b += red2[ww * 16 + tid]; }
        atomicAdd(&g_sum_h [tid], a);
        atomicAdd(&g_sum_h2[tid], b);
    }

    // ---- last block: fold BN1 into W1', b1'; then self-reset scratch ----
    __threadfence();
    __syncthreads();
    if (tid == 0) sLast = (atomicAdd(&g_tick1, 1u) == (unsigned)(gridDim.x - 1));
    __syncthreads();
    if (sLast) {
        __shared__ float sInv[C_HID];
        if (tid < C_HID) {
            float m   = g_sum_h [tid] * (1.f / N_PTS);
            float vv  = g_sum_h2[tid] * (1.f / N_PTS) - m * m;
            float inv = rsqrtf(vv + EPS_BN) * gamma1[tid];
            sInv[tid] = inv;
            g_b1f[tid] = (b1[tid] - m) * inv + beta1[tid];
        }
        __syncthreads();
        for (int idx = tid; idx < C_HID * C_IN; idx += 256)
            g_W1f[idx] = W1[idx] * sInv[idx >> 5];
        if (tid < C_HID) { g_sum_h[tid] = 0.f; g_sum_h2[tid] = 0.f; }
        if (tid == 0)    g_tick1 = 0u;
    }
}

// ---- pass2: staged tile + paired-point attention/accumulation -------------
__global__ void __launch_bounds__(256, 5)
pass2_kernel(const float* __restrict__ x,
             const float* __restrict__ W2,
             const float* __restrict__ b2,
             const float* __restrict__ gamma2,
             const float* __restrict__ beta2,
             const int*   __restrict__ length,
             float*       __restrict__ out) {
    __shared__ __align__(16) float4 sx[TP * 8];   // 16 KB tile
    __shared__ float r_axa[8][C_IN];
    __shared__ float r_ax [8][C_IN];
    __shared__ float r_sa [8];
    __shared__ float r_sa2[8];
    __shared__ bool  sLast;
    int tid  = threadIdx.x;
    int lane = tid & 31;
    int w    = tid >> 5;
    int j    = lane & 15;
    int h    = lane >> 4;

    const float4* wp = (const float4*)(g_W1f + j * C_IN + h * 16);
    float4 w0 = wp[0], w1 = wp[1], w2 = wp[2], w3 = wp[3];
    float  bj  = (h == 0) ? g_b1f[j] : 0.f;
    float  w2j = W2[j];
    float  b20 = b2[0];

    int seg   = blockIdx.x / BPS;
    int blk   = blockIdx.x % BPS;
    int start = seg * PTS + blk * CHUNK2;
    int end   = min(seg * PTS + PTS, start + CHUNK2);
    // all tile sizes even -> pairs never straddle

    const float* sxf = (const float*)sx;
    float sa = 0.f, sa2 = 0.f, axa = 0.f, ax = 0.f;

    for (int ts = start; ts < end; ts += TP) {
        int tn = min(TP, end - ts);
        // ---- stage tile ----
        const float4* src = (const float4*)(x + (size_t)ts * C_IN);
        int nf = tn * 8;
        for (int f = tid; f < nf; f += 256) sx[f] = src[f];
        __syncthreads();
        // ---- paired-point compute from smem ----
        for (int p = 2 * w; p < tn; p += 16) {     // warp-uniform trips
            const float4* xv0 = &sx[p * 8 + h * 4];
            const float4* xv1 = xv0 + 8;
            float4 v;
            float p0a = bj, p0b = 0.f, p1a = bj, p1b = 0.f;
            v = xv0[0]; p0a = fmaf(v.x,w0.x,p0a); p0a = fmaf(v.y,w0.y,p0a); p0a = fmaf(v.z,w0.z,p0a); p0a = fmaf(v.w,w0.w,p0a);
            v = xv0[1]; p0b = fmaf(v.x,w1.x,p0b); p0b = fmaf(v.y,w1.y,p0b); p0b = fmaf(v.z,w1.z,p0b); p0b = fmaf(v.w,w1.w,p0b);
            v = xv0[2]; p0a = fmaf(v.x,w2.x,p0a); p0a = fmaf(v.y,w2.y,p0a); p0a = fmaf(v.z,w2.z,p0a); p0a = fmaf(v.w,w2.w,p0a);
            v = xv0[3]; p0b = fmaf(v.x,w3.x,p0b); p0b = fmaf(v.y,w3.y,p0b); p0b = fmaf(v.z,w3.z,p0b); p0b = fmaf(v.w,w3.w,p0b);
            v = xv1[0]; p1a = fmaf(v.x,w0.x,p1a); p1a = fmaf(v.y,w0.y,p1a); p1a = fmaf(v.z,w0.z,p1a); p1a = fmaf(v.w,w0.w,p1a);
            v = xv1[1]; p1b = fmaf(v.x,w1.x,p1b); p1b = fmaf(v.y,w1.y,p1b); p1b = fmaf(v.z,w1.z,p1b); p1b = fmaf(v.w,w1.w,p1b);
            v = xv1[2]; p1a = fmaf(v.x,w2.x,p1a); p1a = fmaf(v.y,w2.y,p1a); p1a = fmaf(v.z,w2.z,p1a); p1a = fmaf(v.w,w2.w,p1a);
            v = xv1[3]; p1b = fmaf(v.x,w3.x,p1b); p1b = fmaf(v.y,w3.y,p1b); p1b = fmaf(v.z,w3.z,p1b); p1b = fmaf(v.w,w3.w,p1b);
            float s0 = p0a + p0b;
            float s1 = p1a + p1b;
            s0 += __shfl_xor_sync(0xffffffffu, s0, 16);
            s1 += __shfl_xor_sync(0xffffffffu, s1, 16);
            float r0 = fmaxf(s0, 0.f) * w2j;
            float r1 = fmaxf(s1, 0.f) * w2j;
            float t  = (h == 0) ? r0 : r1;          // both reductions at once
            t += __shfl_xor_sync(0xffffffffu, t, 8);
            t += __shfl_xor_sync(0xffffffffu, t, 4);
            t += __shfl_xor_sync(0xffffffffu, t, 2);
            t += __shfl_xor_sync(0xffffffffu, t, 1);
            float other = __shfl_xor_sync(0xffffffffu, t, 16);
            float a0 = ((h == 0) ? t : other) + b20;
            float a1 = ((h == 0) ? other : t) + b20;
            float xl0 = sxf[p * 32 + lane];         // conflict-free LDS
            float xl1 = sxf[p * 32 + 32 + lane];
            axa = fmaf(xl0, a0, axa);
            axa = fmaf(xl1, a1, axa);
            ax += xl0 + xl1;
            if (lane == 0) {
                sa += a0 + a1;
                sa2 = fmaf(a0, a0, sa2);
                sa2 = fmaf(a1, a1, sa2);
            }
        }
        __syncthreads();
    }

    // ---- block reduction + global atomics ----
    r_axa[w][lane] = axa;
    r_ax [w][lane] = ax;
    if (lane == 0) { r_sa[w] = sa; r_sa2[w] = sa2; }
    __syncthreads();
    if (tid < C_IN) {
        float A = 0.f, X = 0.f;
#pragma unroll
        for (int g = 0; g < 8; g++) { A += r_axa[g][tid]; X += r_ax[g][tid]; }
        atomicAdd(&g_seg_xa[seg][tid], A);
        atomicAdd(&g_seg_x [seg][tid], X);
    } else if (tid == C_IN) {
        float S = 0.f;
#pragma unroll
        for (int k = 0; k < 8; k++) S += r_sa[k];
        atomicAdd(&g_sum_a, S);
    } else if (tid == C_IN + 1) {
        float S = 0.f;
#pragma unroll
        for (int k = 0; k < 8; k++) S += r_sa2[k];
        atomicAdd(&g_sum_a2, S);
    }

    // ---- last block: BN2 affine + L2 normalize; then self-reset scratch ---
    __threadfence();
    __syncthreads();
    if (tid == 0) sLast = (atomicAdd(&g_tick2, 1u) == (unsigned)(gridDim.x - 1));
    __syncthreads();
    if (sLast) {
        float m     = g_sum_a  * (1.f / N_PTS);
        float v     = g_sum_a2 * (1.f / N_PTS) - m * m;
        float alpha = rsqrtf(v + EPS_BN) * gamma2[0];
        float betaC = beta2[0] - m * alpha;
#pragma unroll
        for (int half = 0; half < 2; half++) {
            int b = w + half * 8;
            float cnt = (float)length[b];
            float val = (alpha * g_seg_xa[b][lane] + betaC * g_seg_x[b][lane]) / cnt;
            float sq = val * val;
#pragma unroll
            for (int o = 16; o > 0; o >>= 1) sq += __shfl_xor_sync(0xffffffffu, sq, o);
            out[b * C_IN + lane] = val / fmaxf(sqrtf(sq), EPS_NRM);
        }
        __syncthreads();
        for (int i2 = tid; i2 < B_SEG * C_IN; i2 += 256) {
            ((float*)g_seg_xa)[i2] = 0.f;
            ((float*)g_seg_x )[i2] = 0.f;
        }
        if (tid == 0) { g_sum_a = 0.f; g_sum_a2 = 0.f; g_tick2 = 0u; }
    }
}

// ---------------------------------------------------------------- launch --
extern "C" void kernel_launch(void* const* d_in, const int* in_sizes, int n_in,
                              void* d_out, int out_size) {
    const float* x      = (const float*)d_in[0];
    const float* W1     = (const float*)d_in[1];
    const float* b1     = (const float*)d_in[2];
    const float* gamma1 = (const float*)d_in[3];
    const float* beta1  = (const float*)d_in[4];
    const float* W2     = (const float*)d_in[5];
    const float* b2     = (const float*)d_in[6];
    const float* gamma2 = (const float*)d_in[7];
    const float* beta2  = (const float*)d_in[8];
    const int* length   = (const int*)d_in[10];
    float* out          = (float*)d_out;

    pass1_kernel<<<GRID1, 256>>>(x, W1, b1, gamma1, beta1);
    pass2_kernel<<<GRID2, 256>>>(x, W2, b2, gamma2, beta2, length, out);
}

// round 12
// speedup vs baseline: 2.2364x; 1.0784x over previous
#include <cuda_runtime.h>

#define N_PTS   800000
#define B_SEG   16
#define PTS     50000
#define C_IN    32
#define C_HID   16
#define EPS_BN  1e-5f
#define EPS_NRM 1e-12f

#define TP      256                              // points per tile
#define TPAD    257                              // padded point stride (words)

#define GRID1   592                              // 4 blocks/SM, 1 wave
#define CHUNK1  1352                             // 591*1352+968 = 800000

#define BPS     37
#define GRID2   (B_SEG * BPS)                    // 592
#define CHUNK2  1352                             // 36*1352+1328 = 50000

// ---------------- device scratch (zero-init at load; self-reset each run) --
__device__ float g_sum_h [C_HID];
__device__ float g_sum_h2[C_HID];
__device__ float g_W1f   [C_HID * C_IN];
__device__ float g_b1f   [C_HID];
__device__ float g_sum_a;
__device__ float g_sum_a2;
__device__ float g_seg_xa[B_SEG][C_IN];
__device__ float g_seg_x [B_SEG][C_IN];
__device__ unsigned g_tick1, g_tick2;

// Stage rows [ts, ts+tn) of x into TRANSPOSED smem sxT[c][p] (pad TPAD).
// LDG.128 coalesced; STS.32 conflict-free (257 ≡ 1 mod 32).
__device__ __forceinline__ void stage_tile(const float* __restrict__ x,
                                           float* sxT, int ts, int tn, int tid) {
    const float4* src = (const float4*)(x + (size_t)ts * C_IN);
    int nf = tn * 8;
    for (int f = tid; f < nf; f += 256) {
        float4 v = src[f];
        int row = f >> 3, q = f & 7;
        float* d = sxT + (q * 4) * TPAD + row;
        d[0]        = v.x;
        d[TPAD]     = v.y;
        d[2 * TPAD] = v.z;
        d[3 * TPAD] = v.w;
    }
}

// -------------------- pass1: Sum h, Sum h^2, then fold BN1 (last block) ----
// Per-thread-point: thread owns one point (X in 32 regs), computes h_j for
// all j; h staged through hs[8][TP] in two j-halves; warp w reduces
// channels w and w+8. No shuffles in any divergent region.
__global__ void __launch_bounds__(256, 4)
pass1_kernel(const float* __restrict__ x,
             const float* __restrict__ W1,
             const float* __restrict__ b1,
             const float* __restrict__ gamma1,
             const float* __restrict__ beta1) {
    __shared__ float sxT[C_IN * TPAD];            // 32.9 KB
    __shared__ float hs[8][TP];                   // 8 KB
    __shared__ float sW[C_HID * C_IN];            // 2 KB
    __shared__ float sb[C_HID];
    __shared__ bool  sLast;
    int tid  = threadIdx.x;
    int lane = tid & 31;
    int w    = tid >> 5;

    for (int i = tid; i < C_HID * C_IN; i += 256) sW[i] = W1[i];
    if (tid < C_HID) sb[tid] = b1[tid];

    int start = blockIdx.x * CHUNK1;
    int end   = min(N_PTS, start + CHUNK1);

    float shA = 0.f, sh2A = 0.f, shB = 0.f, sh2B = 0.f;  // channels w, w+8
    __syncthreads();

    for (int ts = start; ts < end; ts += TP) {
        int tn = min(TP, end - ts);
        stage_tile(x, sxT, ts, tn, tid);
        __syncthreads();

        float X[32];
        if (tid < tn) {
#pragma unroll
            for (int c = 0; c < 32; c++) X[c] = sxT[c * TPAD + tid];
#pragma unroll 1
            for (int j = 0; j < 8; j++) {
                const float4* wr = (const float4*)(sW + j * C_IN);
                float s0 = 0.f, s1 = 0.f, s2 = 0.f, s3 = 0.f;
#pragma unroll
                for (int q = 0; q < 8; q++) {
                    float4 wv = wr[q];
                    s0 = fmaf(X[4*q+0], wv.x, s0); s1 = fmaf(X[4*q+1], wv.y, s1);
                    s2 = fmaf(X[4*q+2], wv.z, s2); s3 = fmaf(X[4*q+3], wv.w, s3);
                }
                hs[j][tid] = (s0 + s1) + (s2 + s3) + sb[j];
            }
        }
        __syncthreads();
        for (int p = lane; p < tn; p += 32) {     // channel w
            float s = hs[w][p]; shA += s; sh2A = fmaf(s, s, sh2A);
        }
        __syncthreads();                          // hs consumed
        if (tid < tn) {
#pragma unroll 1
            for (int j = 0; j < 8; j++) {
                const float4* wr = (const float4*)(sW + (j + 8) * C_IN);
                float s0 = 0.f, s1 = 0.f, s2 = 0.f, s3 = 0.f;
#pragma unroll
                for (int q = 0; q < 8; q++) {
                    float4 wv = wr[q];
                    s0 = fmaf(X[4*q+0], wv.x, s0); s1 = fmaf(X[4*q+1], wv.y, s1);
                    s2 = fmaf(X[4*q+2], wv.z, s2); s3 = fmaf(X[4*q+3], wv.w, s3);
                }
                hs[j][tid] = (s0 + s1) + (s2 + s3) + sb[j + 8];
            }
        }
        __syncthreads();
        for (int p = lane; p < tn; p += 32) {     // channel w+8
            float s = hs[w][p]; shB += s; sh2B = fmaf(s, s, sh2B);
        }
        __syncthreads();                          // before next staging
    }

    // warp butterfly (uniform, outside all loops): totals for chan w / w+8
#pragma unroll
    for (int o = 16; o > 0; o >>= 1) {
        shA  += __shfl_xor_sync(0xffffffffu, shA,  o);
        sh2A += __shfl_xor_sync(0xffffffffu, sh2A, o);
        shB  += __shfl_xor_sync(0xffffffffu, shB,  o);
        sh2B += __shfl_xor_sync(0xffffffffu, sh2B, o);
    }
    if (lane == 0) {
        atomicAdd(&g_sum_h [w],     shA);
        atomicAdd(&g_sum_h2[w],     sh2A);
        atomicAdd(&g_sum_h [w + 8], shB);
        atomicAdd(&g_sum_h2[w + 8], sh2B);
    }

    // ---- last block: fold BN1 into W1', b1'; then self-reset scratch ----
    __threadfence();
    __syncthreads();
    if (tid == 0) sLast = (atomicAdd(&g_tick1, 1u) == (unsigned)(gridDim.x - 1));
    __syncthreads();
    if (sLast) {
        __shared__ float sInv[C_HID];
        if (tid < C_HID) {
            float m   = g_sum_h [tid] * (1.f / N_PTS);
            float vv  = g_sum_h2[tid] * (1.f / N_PTS) - m * m;
            float inv = rsqrtf(vv + EPS_BN) * gamma1[tid];
            sInv[tid] = inv;
            g_b1f[tid] = (b1[tid] - m) * inv + beta1[tid];
        }
        __syncthreads();
        for (int idx = tid; idx < C_HID * C_IN; idx += 256)
            g_W1f[idx] = W1[idx] * sInv[idx >> 5];
        if (tid < C_HID) { g_sum_h[tid] = 0.f; g_sum_h2[tid] = 0.f; }
        if (tid == 0)    g_tick1 = 0u;
    }
}

// ---- pass2: per-thread-point attention + channel-split accumulation -------
__global__ void __launch_bounds__(256, 4)
pass2_kernel(const float* __restrict__ x,
             const float* __restrict__ W2,
             const float* __restrict__ b2,
             const float* __restrict__ gamma2,
             const float* __restrict__ beta2,
             const int*   __restrict__ length,
             float*       __restrict__ out) {
    __shared__ float  sxT[C_IN * TPAD];           // 32.9 KB
    __shared__ float  sW[C_HID * C_IN];           // 2 KB (folded W1')
    __shared__ float2 sbw[C_HID];                 // (b1f, w2)
    __shared__ float  as_[TP];
    __shared__ float  r_axa[8][C_IN];
    __shared__ float  r_ax [8][C_IN];
    __shared__ float  r_sa [8];
    __shared__ float  r_sa2[8];
    __shared__ bool   sLast;
    int tid  = threadIdx.x;
    int lane = tid & 31;
    int w    = tid >> 5;

    for (int i = tid; i < C_HID * C_IN; i += 256) sW[i] = g_W1f[i];
    if (tid < C_HID) sbw[tid] = make_float2(g_b1f[tid], W2[tid]);
    float b20 = b2[0];

    int seg   = blockIdx.x / BPS;
    int blk   = blockIdx.x % BPS;
    int start = seg * PTS + blk * CHUNK2;
    int end   = min(seg * PTS + PTS, start + CHUNK2);

    float sa = 0.f, sa2 = 0.f, axa = 0.f, ax = 0.f;
    __syncthreads();

    for (int ts = start; ts < end; ts += TP) {
        int tn = min(TP, end - ts);
        stage_tile(x, sxT, ts, tn, tid);
        __syncthreads();

        if (tid < tn) {                            // thread = one point
            float X[32];
#pragma unroll
            for (int c = 0; c < 32; c++) X[c] = sxT[c * TPAD + tid];
            float r = b20;
#pragma unroll 1
            for (int j = 0; j < C_HID; j++) {
                const float4* wr = (const float4*)(sW + j * C_IN);
                float s0 = 0.f, s1 = 0.f, s2 = 0.f, s3 = 0.f;
#pragma unroll
                for (int q = 0; q < 8; q++) {
                    float4 wv = wr[q];
                    s0 = fmaf(X[4*q+0], wv.x, s0); s1 = fmaf(X[4*q+1], wv.y, s1);
                    s2 = fmaf(X[4*q+2], wv.z, s2); s3 = fmaf(X[4*q+3], wv.w, s3);
                }
                float2 bw = sbw[j];
                float s = (s0 + s1) + (s2 + s3) + bw.x;
                r = fmaf(fmaxf(s, 0.f), bw.y, r);
            }
            as_[tid] = r;                          // a for this point
            sa += r;
            sa2 = fmaf(r, r, sa2);
        }
        __syncthreads();

        // channel-split accumulation: warp w takes points w, w+8, ...
        for (int p = w; p < tn; p += 8) {
            float a  = as_[p];                     // broadcast
            float xv = sxT[lane * TPAD + p];       // conflict-free (257%32=1)
            axa = fmaf(xv, a, axa);
            ax += xv;
        }
        __syncthreads();
    }

    // ---- block reduction + global atomics ----
    r_axa[w][lane] = axa;
    r_ax [w][lane] = ax;
#pragma unroll
    for (int o = 16; o > 0; o >>= 1) {             // uniform butterfly
        sa  += __shfl_xor_sync(0xffffffffu, sa,  o);
        sa2 += __shfl_xor_sync(0xffffffffu, sa2, o);
    }
    if (lane == 0) { r_sa[w] = sa; r_sa2[w] = sa2; }
    __syncthreads();
    if (tid < C_IN) {
        float A = 0.f, Xs = 0.f;
#pragma unroll
        for (int g = 0; g < 8; g++) { A += r_axa[g][tid]; Xs += r_ax[g][tid]; }
        atomicAdd(&g_seg_xa[seg][tid], A);
        atomicAdd(&g_seg_x [seg][tid], Xs);
    } else if (tid == C_IN) {
        float S = 0.f;
#pragma unroll
        for (int k = 0; k < 8; k++) S += r_sa[k];
        atomicAdd(&g_sum_a, S);
    } else if (tid == C_IN + 1) {
        float S = 0.f;
#pragma unroll
        for (int k = 0; k < 8; k++) S += r_sa2[k];
        atomicAdd(&g_sum_a2, S);
    }

    // ---- last block: BN2 affine + L2 normalize; then self-reset scratch ---
    __threadfence();
    __syncthreads();
    if (tid == 0) sLast = (atomicAdd(&g_tick2, 1u) == (unsigned)(gridDim.x - 1));
    __syncthreads();
    if (sLast) {
        float m     = g_sum_a  * (1.f / N_PTS);
        float v     = g_sum_a2 * (1.f / N_PTS) - m * m;
        float alpha = rsqrtf(v + EPS_BN) * gamma2[0];
        float betaC = beta2[0] - m * alpha;
#pragma unroll
        for (int half = 0; half < 2; half++) {
            int b = w + half * 8;
            float cnt = (float)length[b];
            float val = (alpha * g_seg_xa[b][lane] + betaC * g_seg_x[b][lane]) / cnt;
            float sq = val * val;
#pragma unroll
            for (int o = 16; o > 0; o >>= 1) sq += __shfl_xor_sync(0xffffffffu, sq, o);
            out[b * C_IN + lane] = val / fmaxf(sqrtf(sq), EPS_NRM);
        }
        __syncthreads();
        for (int i2 = tid; i2 < B_SEG * C_IN; i2 += 256) {
            ((float*)g_seg_xa)[i2] = 0.f;
            ((float*)g_seg_x )[i2] = 0.f;
        }
        if (tid == 0) { g_sum_a = 0.f; g_sum_a2 = 0.f; g_tick2 = 0u; }
    }
}

// ---------------------------------------------------------------- launch --
extern "C" void kernel_launch(void* const* d_in, const int* in_sizes, int n_in,
                              void* d_out, int out_size) {
    const float* x      = (const float*)d_in[0];
    const float* W1     = (const float*)d_in[1];
    const float* b1     = (const float*)d_in[2];
    const float* gamma1 = (const float*)d_in[3];
    const float* beta1  = (const float*)d_in[4];
    const float* W2     = (const float*)d_in[5];
    const float* b2     = (const float*)d_in[6];
    const float* gamma2 = (const float*)d_in[7];
    const float* beta2  = (const float*)d_in[8];
    const int* length   = (const int*)d_in[10];
    float* out          = (float*)d_out;

    pass1_kernel<<<GRID1, 256>>>(x, W1, b1, gamma1, beta1);
    pass2_kernel<<<GRID2, 256>>>(x, W2, b2, gamma2, beta2, length, out);
}

// round 13
// speedup vs baseline: 2.6631x; 1.1908x over previous
#include <cuda_runtime.h>
#include <cuda_fp16.h>

#define N_PTS   800000
#define B_SEG   16
#define PTS     50000
#define C_IN    32
#define C_HID   16
#define EPS_BN  1e-5f
#define EPS_NRM 1e-12f

#define TP      256                              // pass1 tile (points)
#define TPAD    257                              // padded point stride (words)

#define GRID1   592                              // 4 blocks/SM, 1 wave
#define CHUNK1  1352                             // 591*1352+968 = 800000

#define BPS     55                               // pass2 blocks per segment
#define GRID2   (B_SEG * BPS)                    // 880 ≈ 6 blocks/SM
#define CHUNK2  910                              // 54*910+860 = 50000
#define TP2     256                              // pass2 tile (points)

// ---------------- device scratch (zero-init at load; self-reset each run) --
__device__ float    g_sum_h [C_HID];
__device__ float    g_sum_h2[C_HID];
__device__ float2   g_aff   [C_HID];             // (gamma/sigma, beta - m*gamma/sigma)
__device__ float    g_sum_a;
__device__ float    g_sum_a2;
__device__ float    g_seg_xa[B_SEG][C_IN];
__device__ float    g_seg_x [B_SEG][C_IN];
__device__ unsigned g_tick1, g_tick2;
__device__ uint4    g_h[N_PTS * 2];              // fp16 h: 16 halves/pt = 25.6MB

// Stage rows [ts, ts+tn) of x into TRANSPOSED smem sxT[c][p] (pad TPAD).
__device__ __forceinline__ void stage_tile(const float* __restrict__ x,
                                           float* sxT, int ts, int tn, int tid) {
    const float4* src = (const float4*)(x + (size_t)ts * C_IN);
    int nf = tn * 8;
    for (int f = tid; f < nf; f += 256) {
        float4 v = src[f];
        int row = f >> 3, q = f & 7;
        float* d = sxT + (q * 4) * TPAD + row;
        d[0]        = v.x;
        d[TPAD]     = v.y;
        d[2 * TPAD] = v.z;
        d[3 * TPAD] = v.w;
    }
}

// -------- pass1: GEMM -> h (stats + fp16 store), BN1 coeffs (last block) ---
__global__ void __launch_bounds__(256, 4)
pass1_kernel(const float* __restrict__ x,
             const float* __restrict__ W1,
             const float* __restrict__ b1,
             const float* __restrict__ gamma1,
             const float* __restrict__ beta1) {
    __shared__ float sxT[C_IN * TPAD];            // 32.9 KB
    __shared__ float hs[8][TP];                   // 8 KB
    __shared__ float sW[C_HID * C_IN];            // 2 KB
    __shared__ float sb[C_HID];
    __shared__ bool  sLast;
    int tid  = threadIdx.x;
    int lane = tid & 31;
    int w    = tid >> 5;

    for (int i = tid; i < C_HID * C_IN; i += 256) sW[i] = W1[i];
    if (tid < C_HID) sb[tid] = b1[tid];

    int start = blockIdx.x * CHUNK1;
    int end   = min(N_PTS, start + CHUNK1);

    float shA = 0.f, sh2A = 0.f, shB = 0.f, sh2B = 0.f;  // channels w, w+8
    __syncthreads();

    for (int ts = start; ts < end; ts += TP) {
        int tn = min(TP, end - ts);
        stage_tile(x, sxT, ts, tn, tid);
        __syncthreads();

        float X[32];
        if (tid < tn) {
#pragma unroll
            for (int c = 0; c < 32; c++) X[c] = sxT[c * TPAD + tid];
#pragma unroll 1
            for (int j = 0; j < 8; j++) {
                const float4* wr = (const float4*)(sW + j * C_IN);
                float s0 = 0.f, s1 = 0.f, s2 = 0.f, s3 = 0.f;
#pragma unroll
                for (int q = 0; q < 8; q++) {
                    float4 wv = wr[q];
                    s0 = fmaf(X[4*q+0], wv.x, s0); s1 = fmaf(X[4*q+1], wv.y, s1);
                    s2 = fmaf(X[4*q+2], wv.z, s2); s3 = fmaf(X[4*q+3], wv.w, s3);
                }
                hs[j][tid] = (s0 + s1) + (s2 + s3) + sb[j];
            }
        }
        __syncthreads();
        for (int p = lane; p < tn; p += 32) {     // stats, channel w
            float s = hs[w][p]; shA += s; sh2A = fmaf(s, s, sh2A);
        }
        if (tid < tn) {                            // pack h[0..7] -> fp16
            __half2 a0 = __floats2half2_rn(hs[0][tid], hs[1][tid]);
            __half2 a1 = __floats2half2_rn(hs[2][tid], hs[3][tid]);
            __half2 a2 = __floats2half2_rn(hs[4][tid], hs[5][tid]);
            __half2 a3 = __floats2half2_rn(hs[6][tid], hs[7][tid]);
            g_h[(size_t)(ts + tid) * 2] = make_uint4(
                *(unsigned*)&a0, *(unsigned*)&a1, *(unsigned*)&a2, *(unsigned*)&a3);
        }
        __syncthreads();                          // hs consumed
        if (tid < tn) {
#pragma unroll 1
            for (int j = 0; j < 8; j++) {
                const float4* wr = (const float4*)(sW + (j + 8) * C_IN);
                float s0 = 0.f, s1 = 0.f, s2 = 0.f, s3 = 0.f;
#pragma unroll
                for (int q = 0; q < 8; q++) {
                    float4 wv = wr[q];
                    s0 = fmaf(X[4*q+0], wv.x, s0); s1 = fmaf(X[4*q+1], wv.y, s1);
                    s2 = fmaf(X[4*q+2], wv.z, s2); s3 = fmaf(X[4*q+3], wv.w, s3);
                }
                hs[j][tid] = (s0 + s1) + (s2 + s3) + sb[j + 8];
            }
        }
        __syncthreads();
        for (int p = lane; p < tn; p += 32) {     // stats, channel w+8
            float s = hs[w][p]; shB += s; sh2B = fmaf(s, s, sh2B);
        }
        if (tid < tn) {                            // pack h[8..15] -> fp16
            __half2 a0 = __floats2half2_rn(hs[0][tid], hs[1][tid]);
            __half2 a1 = __floats2half2_rn(hs[2][tid], hs[3][tid]);
            __half2 a2 = __floats2half2_rn(hs[4][tid], hs[5][tid]);
            __half2 a3 = __floats2half2_rn(hs[6][tid], hs[7][tid]);
            g_h[(size_t)(ts + tid) * 2 + 1] = make_uint4(
                *(unsigned*)&a0, *(unsigned*)&a1, *(unsigned*)&a2, *(unsigned*)&a3);
        }
        __syncthreads();                          // before next staging
    }

    // warp butterfly (uniform, outside all loops)
#pragma unroll
    for (int o = 16; o > 0; o >>= 1) {
        shA  += __shfl_xor_sync(0xffffffffu, shA,  o);
        sh2A += __shfl_xor_sync(0xffffffffu, sh2A, o);
        shB  += __shfl_xor_sync(0xffffffffu, shB,  o);
        sh2B += __shfl_xor_sync(0xffffffffu, sh2B, o);
    }
    if (lane == 0) {
        atomicAdd(&g_sum_h [w],     shA);
        atomicAdd(&g_sum_h2[w],     sh2A);
        atomicAdd(&g_sum_h [w + 8], shB);
        atomicAdd(&g_sum_h2[w + 8], sh2B);
    }

    // ---- last block: BN1 affine coefficients; then self-reset scratch ----
    __threadfence();
    __syncthreads();
    if (tid == 0) sLast = (atomicAdd(&g_tick1, 1u) == (unsigned)(gridDim.x - 1));
    __syncthreads();
    if (sLast) {
        if (tid < C_HID) {
            float m   = g_sum_h [tid] * (1.f / N_PTS);
            float vv  = g_sum_h2[tid] * (1.f / N_PTS) - m * m;
            float inv = rsqrtf(vv + EPS_BN) * gamma1[tid];
            g_aff[tid] = make_float2(inv, beta1[tid] - m * inv);
            g_sum_h[tid] = 0.f; g_sum_h2[tid] = 0.f;
        }
        if (tid == 0) g_tick1 = 0u;
    }
}

// ---- pass2: a from stored fp16 h; direct-coalesced x accumulation ---------
__global__ void __launch_bounds__(256, 6)
pass2_kernel(const float* __restrict__ x,
             const float* __restrict__ W2,
             const float* __restrict__ b2,
             const float* __restrict__ gamma2,
             const float* __restrict__ beta2,
             const int*   __restrict__ length,
             float*       __restrict__ out) {
    __shared__ float2 saff[C_HID];
    __shared__ float  sw2[C_HID];
    __shared__ float  as_[TP2];
    __shared__ float  r_axa[8][C_IN];
    __shared__ float  r_ax [8][C_IN];
    __shared__ float  r_sa [8];
    __shared__ float  r_sa2[8];
    __shared__ bool   sLast;
    int tid  = threadIdx.x;
    int lane = tid & 31;
    int w    = tid >> 5;

    if (tid < C_HID) { saff[tid] = g_aff[tid]; sw2[tid] = W2[tid]; }
    float b20 = b2[0];

    int seg   = blockIdx.x / BPS;
    int blk   = blockIdx.x % BPS;
    int start = seg * PTS + blk * CHUNK2;
    int end   = min(seg * PTS + PTS, start + CHUNK2);

    float sa = 0.f, sa2 = 0.f, axa = 0.f, ax = 0.f;
    __syncthreads();

    for (int ts = start; ts < end; ts += TP2) {
        int tn = min(TP2, end - ts);
        if (tid < tn) {                            // thread = one point
            uint4 u0 = g_h[(size_t)(ts + tid) * 2];
            uint4 u1 = g_h[(size_t)(ts + tid) * 2 + 1];
            unsigned hw[8] = {u0.x, u0.y, u0.z, u0.w, u1.x, u1.y, u1.z, u1.w};
            float r = b20;
#pragma unroll
            for (int k = 0; k < 8; k++) {
                float2 f  = __half22float2(*(__half2*)&hw[k]);
                float2 A0 = saff[2 * k], A1 = saff[2 * k + 1];
                float s0 = fmaf(f.x, A0.x, A0.y);
                float s1 = fmaf(f.y, A1.x, A1.y);
                r = fmaf(fmaxf(s0, 0.f), sw2[2 * k],     r);
                r = fmaf(fmaxf(s1, 0.f), sw2[2 * k + 1], r);
            }
            as_[tid] = r;
            sa += r;
            sa2 = fmaf(r, r, sa2);
        }
        __syncthreads();

        // channel-split accumulation: warp w takes points w, w+8, ...
        for (int p = w; p < tn; p += 8) {
            float a  = as_[p];                     // smem broadcast
            float xv = x[(size_t)(ts + p) * C_IN + lane];  // coalesced LDG
            axa = fmaf(xv, a, axa);
            ax += xv;
        }
        __syncthreads();
    }

    // ---- block reduction + global atomics ----
    r_axa[w][lane] = axa;
    r_ax [w][lane] = ax;
#pragma unroll
    for (int o = 16; o > 0; o >>= 1) {             // uniform butterfly
        sa  += __shfl_xor_sync(0xffffffffu, sa,  o);
        sa2 += __shfl_xor_sync(0xffffffffu, sa2, o);
    }
    if (lane == 0) { r_sa[w] = sa; r_sa2[w] = sa2; }
    __syncthreads();
    if (tid < C_IN) {
        float A = 0.f, Xs = 0.f;
#pragma unroll
        for (int g = 0; g < 8; g++) { A += r_axa[g][tid]; Xs += r_ax[g][tid]; }
        atomicAdd(&g_seg_xa[seg][tid], A);
        atomicAdd(&g_seg_x [seg][tid], Xs);
    } else if (tid == C_IN) {
        float S = 0.f;
#pragma unroll
        for (int k = 0; k < 8; k++) S += r_sa[k];
        atomicAdd(&g_sum_a, S);
    } else if (tid == C_IN + 1) {
        float S = 0.f;
#pragma unroll
        for (int k = 0; k < 8; k++) S += r_sa2[k];
        atomicAdd(&g_sum_a2, S);
    }

    // ---- last block: BN2 affine + L2 normalize; then self-reset scratch ---
    __threadfence();
    __syncthreads();
    if (tid == 0) sLast = (atomicAdd(&g_tick2, 1u) == (unsigned)(gridDim.x - 1));
    __syncthreads();
    if (sLast) {
        float m     = g_sum_a  * (1.f / N_PTS);
        float v     = g_sum_a2 * (1.f / N_PTS) - m * m;
        float alpha = rsqrtf(v + EPS_BN) * gamma2[0];
        float betaC = beta2[0] - m * alpha;
#pragma unroll
        for (int half = 0; half < 2; half++) {
            int b = w + half * 8;
            float cnt = (float)length[b];
            float val = (alpha * g_seg_xa[b][lane] + betaC * g_seg_x[b][lane]) / cnt;
            float sq = val * val;
#pragma unroll
            for (int o = 16; o > 0; o >>= 1) sq += __shfl_xor_sync(0xffffffffu, sq, o);
            out[b * C_IN + lane] = val / fmaxf(sqrtf(sq), EPS_NRM);
        }
        __syncthreads();
        for (int i2 = tid; i2 < B_SEG * C_IN; i2 += 256) {
            ((float*)g_seg_xa)[i2] = 0.f;
            ((float*)g_seg_x )[i2] = 0.f;
        }
        if (tid == 0) { g_sum_a = 0.f; g_sum_a2 = 0.f; g_tick2 = 0u; }
    }
}

// ---------------------------------------------------------------- launch --
extern "C" void kernel_launch(void* const* d_in, const int* in_sizes, int n_in,
                              void* d_out, int out_size) {
    const float* x      = (const float*)d_in[0];
    const float* W1     = (const float*)d_in[1];
    const float* b1     = (const float*)d_in[2];
    const float* gamma1 = (const float*)d_in[3];
    const float* beta1  = (const float*)d_in[4];
    const float* W2     = (const float*)d_in[5];
    const float* b2     = (const float*)d_in[6];
    const float* gamma2 = (const float*)d_in[7];
    const float* beta2  = (const float*)d_in[8];
    const int* length   = (const int*)d_in[10];
    float* out          = (float*)d_out;

    pass1_kernel<<<GRID1, 256>>>(x, W1, b1, gamma1, beta1);
    pass2_kernel<<<GRID2, 256>>>(x, W2, b2, gamma2, beta2, length, out);
}